// round 10
// baseline (speedup 1.0000x reference)
#include <cuda_runtime.h>
#include <cuda_bf16.h>
#include <math.h>
#include <stdint.h>

// TopKRouter: x[4,4096,4096] fp32, gate_w[64,4096] fp32
// logits = x @ w^T [16384,64]; softmax; top-2; z_loss = mean(logits^2)
// out fp32: [0,32768) idx | [32768,65536) scores | [65536] aux=0 | [65537] z_loss
//
// sm_103 BASE target. mma.sync bf16 hi/lo split (3 passes). 512 threads split
// into TWO independent 256-thread groups (named barriers), each owning 64 token
// rows with private double-buffered stages (B duplicated per group) so the two
// pipelines decouple. Exact fp32 fixup for ambiguous tokens inlined.

#define M_TOT 16384
#define H_DIM 4096
#define E_NUM 64
#define MT    128
#define KC    64
#define NC    (H_DIM / KC)     // 64
#define NBLK  (M_TOT / MT)     // 128
#define NTHR  512
#define GAP_TH 3e-4f

// per-group layout: group base + stage*32768; AH 0 | AL 8192 | BH 16384 | BL 24576
#define GRP_SZ  65536
#define STG_SZ  32768
#define AH_O 0
#define AL_O 8192
#define BH_O 16384
#define BL_O 24576
#define DSMB (1024 + 2 * GRP_SZ)   // 132096

__device__ float g_partials[NBLK];

__device__ __forceinline__ uint32_t smem_u32(const void* p) {
    uint32_t a;
    asm("{ .reg .u64 t; cvta.to.shared.u64 t, %1; cvt.u32.u64 %0, t; }" : "=r"(a) : "l"(p));
    return a;
}

#define BARG(g) asm volatile("bar.sync %0, %1;" :: "r"(1 + (g)), "r"(256) : "memory")

#define LDM4(r, a) \
    asm volatile("ldmatrix.sync.aligned.m8n8.x4.shared.b16 {%0,%1,%2,%3}, [%4];" \
        : "=r"((r)[0]), "=r"((r)[1]), "=r"((r)[2]), "=r"((r)[3]) : "r"(a))

#define MMA(c, a, b0, b1) \
    asm volatile("mma.sync.aligned.m16n8k16.row.col.f32.bf16.bf16.f32 " \
        "{%0,%1,%2,%3},{%4,%5,%6,%7},{%8,%9},{%0,%1,%2,%3};" \
        : "+f"((c)[0]), "+f"((c)[1]), "+f"((c)[2]), "+f"((c)[3]) \
        : "r"((a)[0]), "r"((a)[1]), "r"((a)[2]), "r"((a)[3]), "r"(b0), "r"(b1))

// split float4 into bf16 hi/lo quads, store 8B each (swizzled, 128B rows)
__device__ __forceinline__ void cvtst(float4 v, uint32_t hi, uint32_t lo, int row, int q) {
    uint32_t off = (uint32_t)row * 128u + (((uint32_t)q * 8u) ^ (((uint32_t)row & 7u) << 4));
    uint32_t h01, h23, l01, l23;
    asm("cvt.rn.bf16x2.f32 %0, %1, %2;" : "=r"(h01) : "f"(v.y), "f"(v.x));
    asm("cvt.rn.bf16x2.f32 %0, %1, %2;" : "=r"(h23) : "f"(v.w), "f"(v.z));
    float hx = __uint_as_float(h01 << 16), hy = __uint_as_float(h01 & 0xffff0000u);
    float hz = __uint_as_float(h23 << 16), hw = __uint_as_float(h23 & 0xffff0000u);
    asm("cvt.rn.bf16x2.f32 %0, %1, %2;" : "=r"(l01) : "f"(v.y - hy), "f"(v.x - hx));
    asm("cvt.rn.bf16x2.f32 %0, %1, %2;" : "=r"(l23) : "f"(v.w - hw), "f"(v.z - hz));
    asm volatile("st.shared.v2.u32 [%0], {%1,%2};" :: "r"(hi + off), "r"(h01), "r"(h23) : "memory");
    asm volatile("st.shared.v2.u32 [%0], {%1,%2};" :: "r"(lo + off), "r"(l01), "r"(l23) : "memory");
}

extern __shared__ char dsm_raw[];

// one chunk for one group: MMA on read-stage; cvt regs(c+1)->write-stage; LDG(c+2)->regs.
// ra/rb: 4 quads each (A rows 0-63 of group, B rows 0-63 = all experts).
template <bool DO_CVT, bool DO_LDG>
__device__ __forceinline__ void chunk_iter(
    int c, const float* __restrict__ x, const float* __restrict__ w,
    int m0g, int gtid, int g, int kgrp, uint32_t GB,
    float4 (&ra)[4], float4 (&rb)[4],
    const uint32_t sxor, const uint32_t aoff0, const uint32_t aoff1, const uint32_t akx,
    const uint32_t boff0, const uint32_t boff1, const uint32_t bkx,
    float (&acc)[2][4][4])
{
    const uint32_t rbuf = GB + ((c & 1) ? STG_SZ : 0);
    const uint32_t wbuf = GB + ((c & 1) ? 0 : STG_SZ);
    const uint32_t AH = rbuf + AH_O, AL = rbuf + AL_O, BH = rbuf + BH_O, BL = rbuf + BL_O;
    const uint32_t AHw = wbuf + AH_O, ALw = wbuf + AL_O, BHw = wbuf + BH_O, BLw = wbuf + BL_O;
    const int k0n2 = (c + 2) * KC;

#pragma unroll
    for (int ks = 0; ks < 2; ks++) {
        const uint32_t kb  = (uint32_t)(kgrp * 2 + ks) * 32u;
        const uint32_t ka  = (kb + akx) ^ sxor;
        const uint32_t kbb = (kb + bkx) ^ sxor;
        uint32_t aH[2][4], aL[2][4];
        LDM4(aH[0], AH + aoff0 + ka);  LDM4(aH[1], AH + aoff1 + ka);
        LDM4(aL[0], AL + aoff0 + ka);  LDM4(aL[1], AL + aoff1 + ka);

#pragma unroll
        for (int nh = 0; nh < 2; nh++) {
            const uint32_t bo = (nh == 0) ? boff0 : boff1;
            uint32_t bHn[4], bLn[4];
            LDM4(bHn, BH + bo + kbb);
            LDM4(bLn, BL + bo + kbb);

            // pass-outer: each acc re-issued every 4 MMAs
#pragma unroll
            for (int mi = 0; mi < 2; mi++)
#pragma unroll
                for (int nl = 0; nl < 2; nl++)
                    MMA(acc[mi][nh * 2 + nl], aH[mi], bHn[nl * 2], bHn[nl * 2 + 1]);
#pragma unroll
            for (int mi = 0; mi < 2; mi++)
#pragma unroll
                for (int nl = 0; nl < 2; nl++)
                    MMA(acc[mi][nh * 2 + nl], aH[mi], bLn[nl * 2], bLn[nl * 2 + 1]);
#pragma unroll
            for (int mi = 0; mi < 2; mi++)
#pragma unroll
                for (int nl = 0; nl < 2; nl++)
                    MMA(acc[mi][nh * 2 + nl], aL[mi], bHn[nl * 2], bHn[nl * 2 + 1]);

            const int slot = ks * 2 + nh;    // 0..3
            if (DO_CVT) {
                int s = gtid + slot * 256;
                cvtst(ra[slot], AHw, ALw, s >> 4, s & 15);
                cvtst(rb[slot], BHw, BLw, s >> 4, s & 15);
            }
            if (DO_LDG) {
                int s = gtid + slot * 256, r = s >> 4, q = s & 15;
                ra[slot] = *(const float4*)&x[(size_t)(m0g + r) * H_DIM + k0n2 + q * 4];
                rb[slot] = *(const float4*)&w[(size_t)r * H_DIM + k0n2 + q * 4];
            }
        }
    }
    BARG(g);
}

__global__ __launch_bounds__(NTHR, 1)
void router_main(const float* __restrict__ x, const float* __restrict__ w,
                 float* __restrict__ out)
{
    __shared__ float zsh[4];
    __shared__ float lg[E_NUM];
    __shared__ int flist[32];
    __shared__ int fcnt;

    const int tid  = threadIdx.x;
    const int lid  = tid & 31;
    const int g    = tid >> 8;           // group 0/1
    const int gtid = tid & 255;
    const int gwid = gtid >> 5;          // warp in group 0..7
    const int kgrp = gwid >> 2;          // k slices {0,1} vs {2,3}
    const int pw   = gwid & 3;
    const int wm   = pw & 1, wn = pw >> 1;   // 32-row x 32-expert warp tile
    const int m0   = blockIdx.x * MT;
    const int m0g  = m0 + g * 64;

    uint32_t raw   = smem_u32(dsm_raw);
    uint32_t sbase = (raw + 127u) & ~127u;
    const uint32_t GB = sbase + (uint32_t)g * GRP_SZ;

    const uint32_t sxor  = ((uint32_t)(lid & 7)) << 4;
    const uint32_t aoff0 = (uint32_t)(wm * 32 + (lid & 15)) * 128u;
    const uint32_t aoff1 = aoff0 + 2048u;
    const uint32_t akx   = ((uint32_t)(lid >> 4)) << 4;
    const uint32_t boff0 = (uint32_t)(wn * 32 + ((lid >> 4) << 3) + (lid & 7)) * 128u;
    const uint32_t boff1 = boff0 + 2048u;
    const uint32_t bkx   = ((uint32_t)((lid >> 3) & 1)) << 4;

    float acc[2][4][4];
#pragma unroll
    for (int mi = 0; mi < 2; mi++)
#pragma unroll
        for (int ni = 0; ni < 4; ni++)
#pragma unroll
            for (int r = 0; r < 4; r++) acc[mi][ni][r] = 0.f;

    if (tid == 0) fcnt = 0;

    float4 ra[4], rb[4];

    // prologue: chunk 0 -> regs -> stage0; chunk 1 -> regs   (group-scoped)
#pragma unroll
    for (int j = 0; j < 4; j++) {
        int s = gtid + j * 256, r = s >> 4, q = s & 15;
        ra[j] = *(const float4*)&x[(size_t)(m0g + r) * H_DIM + q * 4];
        rb[j] = *(const float4*)&w[(size_t)r * H_DIM + q * 4];
    }
    {
        uint32_t AH = GB + AH_O, AL = GB + AL_O, BH = GB + BH_O, BL = GB + BL_O;
#pragma unroll
        for (int j = 0; j < 4; j++) {
            int s = gtid + j * 256;
            cvtst(ra[j], AH, AL, s >> 4, s & 15);
            cvtst(rb[j], BH, BL, s >> 4, s & 15);
        }
    }
    BARG(g);
#pragma unroll
    for (int j = 0; j < 4; j++) {
        int s = gtid + j * 256, r = s >> 4, q = s & 15;
        ra[j] = *(const float4*)&x[(size_t)(m0g + r) * H_DIM + KC + q * 4];
        rb[j] = *(const float4*)&w[(size_t)r * H_DIM + KC + q * 4];
    }

#pragma unroll 1
    for (int c = 0; c < NC - 2; c++)
        chunk_iter<true, true>(c, x, w, m0g, gtid, g, kgrp, GB, ra, rb,
                               sxor, aoff0, aoff1, akx, boff0, boff1, bkx, acc);
    chunk_iter<true,  false>(NC - 2, x, w, m0g, gtid, g, kgrp, GB, ra, rb,
                             sxor, aoff0, aoff1, akx, boff0, boff1, bkx, acc);
    chunk_iter<false, false>(NC - 1, x, w, m0g, gtid, g, kgrp, GB, ra, rb,
                             sxor, aoff0, aoff1, akx, boff0, boff1, bkx, acc);

    // ---- merge kgrp halves + stage logits [64][65] per group (overlays stage0) ----
    float* lsg = (float*)(dsm_raw + (GB - raw));
    {
        int gr = lid >> 2, tg = lid & 3;
        if (kgrp == 0) {
#pragma unroll
            for (int mi = 0; mi < 2; mi++)
#pragma unroll
                for (int ni = 0; ni < 4; ni++) {
                    int r0 = wm * 32 + mi * 16 + gr;
                    int col = wn * 32 + ni * 8 + tg * 2;
                    lsg[r0 * 65 + col]           = acc[mi][ni][0];
                    lsg[r0 * 65 + col + 1]       = acc[mi][ni][1];
                    lsg[(r0 + 8) * 65 + col]     = acc[mi][ni][2];
                    lsg[(r0 + 8) * 65 + col + 1] = acc[mi][ni][3];
                }
        }
        BARG(g);
        if (kgrp == 1) {
#pragma unroll
            for (int mi = 0; mi < 2; mi++)
#pragma unroll
                for (int ni = 0; ni < 4; ni++) {
                    int r0 = wm * 32 + mi * 16 + gr;
                    int col = wn * 32 + ni * 8 + tg * 2;
                    lsg[r0 * 65 + col]           += acc[mi][ni][0];
                    lsg[r0 * 65 + col + 1]       += acc[mi][ni][1];
                    lsg[(r0 + 8) * 65 + col]     += acc[mi][ni][2];
                    lsg[(r0 + 8) * 65 + col + 1] += acc[mi][ni][3];
                }
        }
    }
    __syncthreads();   // all groups' logits visible to all

    // ---- per-token epilogue: threads 0..127 own one token ----
    float zs = 0.f;
    if (tid < MT) {
        const float* ls2 = (const float*)(dsm_raw + (sbase - raw)
                                          + (uint32_t)(tid >> 6) * GRP_SZ);
        int row = tid & 63;
        float m1 = -1e30f, m2 = -1e30f, m3 = -1e30f;
        int i1 = 0, i2 = 0;
#pragma unroll
        for (int j = 0; j < E_NUM; j++) {
            float v = ls2[row * 65 + j];
            zs += v * v;
            if (v > m1)      { m3 = m2; m2 = m1; i2 = i1; m1 = v; i1 = j; }
            else if (v > m2) { m3 = m2; m2 = v; i2 = j; }
            else if (v > m3) { m3 = v; }
        }
        float s = 0.f;
#pragma unroll
        for (int j = 0; j < E_NUM; j++)
            s += expf(ls2[row * 65 + j] - m1);

        int tok = m0 + tid;
        out[tok * 2 + 0] = (float)i1;
        out[tok * 2 + 1] = (float)i2;
        out[2 * M_TOT + tok * 2 + 0] = 1.0f / s;
        out[2 * M_TOT + tok * 2 + 1] = expf(m2 - m1) / s;
        if ((m1 - m2 < GAP_TH) || (m2 - m3 < GAP_TH)) {
            int p = atomicAdd(&fcnt, 1);
            if (p < 32) flist[p] = tid;
        }
    }

    // ---- z partial ----
    if ((tid >> 5) < 4) {
#pragma unroll
        for (int o = 16; o > 0; o >>= 1)
            zs += __shfl_xor_sync(0xffffffffu, zs, o);
        if (lid == 0) zsh[tid >> 5] = zs;
    }
    __syncthreads();
    if (tid == 0)
        g_partials[blockIdx.x] = zsh[0] + zsh[1] + zsh[2] + zsh[3];

    // ---- inline exact fp32 fixup for ambiguous tokens (rare) ----
    int nfix = fcnt < 32 ? fcnt : 32;
    const int wid = tid >> 5;
    for (int i = 0; i < nfix; i++) {
        int tok = m0 + flist[i];
        const float4* xr = (const float4*)(x + (size_t)tok * H_DIM);
#pragma unroll 1
        for (int e4 = 0; e4 < 4; e4++) {
            int e = wid * 4 + e4;
            const float4* wr = (const float4*)(w + (size_t)e * H_DIM);
            float s = 0.f;
#pragma unroll 4
            for (int j = lid; j < H_DIM / 4; j += 32) {
                float4 a = xr[j], b = wr[j];
                s += a.x * b.x + a.y * b.y + a.z * b.z + a.w * b.w;
            }
#pragma unroll
            for (int o = 16; o > 0; o >>= 1)
                s += __shfl_xor_sync(0xffffffffu, s, o);
            if (lid == 0) lg[e] = s;
        }
        __syncthreads();
        if (tid == 0) {
            float m1 = -1e30f, m2 = -1e30f;
            int i1 = 0, i2 = 0;
            for (int j = 0; j < E_NUM; j++) {
                float v = lg[j];
                if (v > m1)      { m2 = m1; i2 = i1; m1 = v; i1 = j; }
                else if (v > m2) { m2 = v; i2 = j; }
            }
            float s2 = 0.f;
            for (int j = 0; j < E_NUM; j++) s2 += expf(lg[j] - m1);
            out[tok * 2 + 0] = (float)i1;
            out[tok * 2 + 1] = (float)i2;
            out[2 * M_TOT + tok * 2 + 0] = 1.0f / s2;
            out[2 * M_TOT + tok * 2 + 1] = expf(m2 - m1) / s2;
        }
        __syncthreads();
    }
}

__global__ __launch_bounds__(128) void router_finalize(float* __restrict__ out)
{
    __shared__ float sh[128];
    int tid = threadIdx.x;
    sh[tid] = g_partials[tid];
    __syncthreads();
#pragma unroll
    for (int s = 64; s > 0; s >>= 1) {
        if (tid < s) sh[tid] += sh[tid + s];
        __syncthreads();
    }
    if (tid == 0) {
        out[4 * M_TOT + 0] = 0.0f;
        out[4 * M_TOT + 1] = sh[0] / ((float)M_TOT * (float)E_NUM);
    }
}

extern "C" void kernel_launch(void* const* d_in, const int* in_sizes, int n_in,
                              void* d_out, int out_size)
{
    const float* x = (const float*)d_in[0];   // [4,4096,4096]
    const float* w = (const float*)d_in[1];   // [64,4096]
    float* out = (float*)d_out;

    cudaFuncSetAttribute(router_main, cudaFuncAttributeMaxDynamicSharedMemorySize, DSMB);
    router_main<<<NBLK, NTHR, DSMB>>>(x, w, out);
    router_finalize<<<1, 128>>>(out);
}

// round 11
// speedup vs baseline: 1.0268x; 1.0268x over previous
#include <cuda_runtime.h>
#include <cuda_bf16.h>
#include <math.h>
#include <stdint.h>

// TopKRouter: x[4,4096,4096] fp32, gate_w[64,4096] fp32
// logits = x @ w^T [16384,64]; softmax; top-2; z_loss = mean(logits^2)
// out fp32: [0,32768) idx | [32768,65536) scores | [65536] aux=0 | [65537] z_loss
//
// sm_103 BASE target. mma.sync bf16 hi/lo split (3 passes).
// MT=64 tokens/CTA, 256 threads, grid=256, 65KB smem -> 2 CTAs/SM co-resident
// (independent pipelines fill each other's latency bubbles; all 148 SMs used).

#define M_TOT 16384
#define H_DIM 4096
#define E_NUM 64
#define MT    64
#define KC    64
#define NC    (H_DIM / KC)     // 64
#define NBLK  (M_TOT / MT)     // 256
#define NTHR  256
#define GAP_TH 3e-4f

// stage layout: AH 0 | AL 8192 | BH 16384 | BL 24576 ; two stages
#define STG_SZ  32768
#define AH_O 0
#define AL_O 8192
#define BH_O 16384
#define BL_O 24576
#define DSMB (1024 + 2 * STG_SZ)   // 66560

__device__ float g_partials[NBLK];

__device__ __forceinline__ uint32_t smem_u32(const void* p) {
    uint32_t a;
    asm("{ .reg .u64 t; cvta.to.shared.u64 t, %1; cvt.u32.u64 %0, t; }" : "=r"(a) : "l"(p));
    return a;
}

#define LDM4(r, a) \
    asm volatile("ldmatrix.sync.aligned.m8n8.x4.shared.b16 {%0,%1,%2,%3}, [%4];" \
        : "=r"((r)[0]), "=r"((r)[1]), "=r"((r)[2]), "=r"((r)[3]) : "r"(a))

#define MMA(c, a, b0, b1) \
    asm volatile("mma.sync.aligned.m16n8k16.row.col.f32.bf16.bf16.f32 " \
        "{%0,%1,%2,%3},{%4,%5,%6,%7},{%8,%9},{%0,%1,%2,%3};" \
        : "+f"((c)[0]), "+f"((c)[1]), "+f"((c)[2]), "+f"((c)[3]) \
        : "r"((a)[0]), "r"((a)[1]), "r"((a)[2]), "r"((a)[3]), "r"(b0), "r"(b1))

// split float4 into bf16 hi/lo quads, store 8B each (swizzled, 128B rows)
__device__ __forceinline__ void cvtst(float4 v, uint32_t hi, uint32_t lo, int row, int q) {
    uint32_t off = (uint32_t)row * 128u + (((uint32_t)q * 8u) ^ (((uint32_t)row & 7u) << 4));
    uint32_t h01, h23, l01, l23;
    asm("cvt.rn.bf16x2.f32 %0, %1, %2;" : "=r"(h01) : "f"(v.y), "f"(v.x));
    asm("cvt.rn.bf16x2.f32 %0, %1, %2;" : "=r"(h23) : "f"(v.w), "f"(v.z));
    float hx = __uint_as_float(h01 << 16), hy = __uint_as_float(h01 & 0xffff0000u);
    float hz = __uint_as_float(h23 << 16), hw = __uint_as_float(h23 & 0xffff0000u);
    asm("cvt.rn.bf16x2.f32 %0, %1, %2;" : "=r"(l01) : "f"(v.y - hy), "f"(v.x - hx));
    asm("cvt.rn.bf16x2.f32 %0, %1, %2;" : "=r"(l23) : "f"(v.w - hw), "f"(v.z - hz));
    asm volatile("st.shared.v2.u32 [%0], {%1,%2};" :: "r"(hi + off), "r"(h01), "r"(h23) : "memory");
    asm volatile("st.shared.v2.u32 [%0], {%1,%2};" :: "r"(lo + off), "r"(l01), "r"(l23) : "memory");
}

extern __shared__ char dsm_raw[];

// one chunk: MMA on read-stage; cvt regs(c+1)->write-stage; LDG(c+2)->regs.
template <bool DO_CVT, bool DO_LDG>
__device__ __forceinline__ void chunk_iter(
    int c, const float* __restrict__ x, const float* __restrict__ w,
    int m0, int tid, int kgrp, uint32_t SB,
    float4 (&ra)[4], float4 (&rb)[4],
    const uint32_t sxor, const uint32_t aoff0, const uint32_t aoff1, const uint32_t akx,
    const uint32_t boff0, const uint32_t boff1, const uint32_t bkx,
    float (&acc)[2][4][4])
{
    const uint32_t rbuf = SB + ((c & 1) ? STG_SZ : 0);
    const uint32_t wbuf = SB + ((c & 1) ? 0 : STG_SZ);
    const uint32_t AH = rbuf + AH_O, AL = rbuf + AL_O, BH = rbuf + BH_O, BL = rbuf + BL_O;
    const uint32_t AHw = wbuf + AH_O, ALw = wbuf + AL_O, BHw = wbuf + BH_O, BLw = wbuf + BL_O;
    const int k0n2 = (c + 2) * KC;

#pragma unroll
    for (int ks = 0; ks < 2; ks++) {
        const uint32_t kb  = (uint32_t)(kgrp * 2 + ks) * 32u;
        const uint32_t ka  = (kb + akx) ^ sxor;
        const uint32_t kbb = (kb + bkx) ^ sxor;
        uint32_t aH[2][4], aL[2][4];
        LDM4(aH[0], AH + aoff0 + ka);  LDM4(aH[1], AH + aoff1 + ka);
        LDM4(aL[0], AL + aoff0 + ka);  LDM4(aL[1], AL + aoff1 + ka);

#pragma unroll
        for (int nh = 0; nh < 2; nh++) {
            const uint32_t bo = (nh == 0) ? boff0 : boff1;
            uint32_t bHn[4], bLn[4];
            LDM4(bHn, BH + bo + kbb);
            LDM4(bLn, BL + bo + kbb);

            // pass-outer: each acc re-issued every 4 MMAs
#pragma unroll
            for (int mi = 0; mi < 2; mi++)
#pragma unroll
                for (int nl = 0; nl < 2; nl++)
                    MMA(acc[mi][nh * 2 + nl], aH[mi], bHn[nl * 2], bHn[nl * 2 + 1]);
#pragma unroll
            for (int mi = 0; mi < 2; mi++)
#pragma unroll
                for (int nl = 0; nl < 2; nl++)
                    MMA(acc[mi][nh * 2 + nl], aH[mi], bLn[nl * 2], bLn[nl * 2 + 1]);
#pragma unroll
            for (int mi = 0; mi < 2; mi++)
#pragma unroll
                for (int nl = 0; nl < 2; nl++)
                    MMA(acc[mi][nh * 2 + nl], aL[mi], bHn[nl * 2], bHn[nl * 2 + 1]);

            const int slot = ks * 2 + nh;    // 0..3
            if (DO_CVT) {
                int s = tid + slot * NTHR;
                cvtst(ra[slot], AHw, ALw, s >> 4, s & 15);
                cvtst(rb[slot], BHw, BLw, s >> 4, s & 15);
            }
            if (DO_LDG) {
                int s = tid + slot * NTHR, r = s >> 4, q = s & 15;
                ra[slot] = *(const float4*)&x[(size_t)(m0 + r) * H_DIM + k0n2 + q * 4];
                rb[slot] = *(const float4*)&w[(size_t)r * H_DIM + k0n2 + q * 4];
            }
        }
    }
    __syncthreads();
}

__global__ __launch_bounds__(NTHR, 2)
void router_main(const float* __restrict__ x, const float* __restrict__ w,
                 float* __restrict__ out)
{
    __shared__ float zsh[2];
    __shared__ float lg[E_NUM];
    __shared__ int flist[16];
    __shared__ int fcnt;

    const int tid  = threadIdx.x;
    const int lid  = tid & 31;
    const int wid  = tid >> 5;           // 0..7
    const int kgrp = wid >> 2;           // k slices {0,1} vs {2,3}
    const int pw   = wid & 3;
    const int wm   = pw & 1, wn = pw >> 1;   // 32-row x 32-expert warp tile
    const int m0   = blockIdx.x * MT;

    uint32_t raw   = smem_u32(dsm_raw);
    uint32_t SB    = (raw + 127u) & ~127u;

    const uint32_t sxor  = ((uint32_t)(lid & 7)) << 4;
    const uint32_t aoff0 = (uint32_t)(wm * 32 + (lid & 15)) * 128u;
    const uint32_t aoff1 = aoff0 + 2048u;
    const uint32_t akx   = ((uint32_t)(lid >> 4)) << 4;
    const uint32_t boff0 = (uint32_t)(wn * 32 + ((lid >> 4) << 3) + (lid & 7)) * 128u;
    const uint32_t boff1 = boff0 + 2048u;
    const uint32_t bkx   = ((uint32_t)((lid >> 3) & 1)) << 4;

    float acc[2][4][4];
#pragma unroll
    for (int mi = 0; mi < 2; mi++)
#pragma unroll
        for (int ni = 0; ni < 4; ni++)
#pragma unroll
            for (int r = 0; r < 4; r++) acc[mi][ni][r] = 0.f;

    if (tid == 0) fcnt = 0;

    float4 ra[4], rb[4];

    // prologue: chunk 0 -> regs -> stage0; chunk 1 -> regs
#pragma unroll
    for (int j = 0; j < 4; j++) {
        int s = tid + j * NTHR, r = s >> 4, q = s & 15;
        ra[j] = *(const float4*)&x[(size_t)(m0 + r) * H_DIM + q * 4];
        rb[j] = *(const float4*)&w[(size_t)r * H_DIM + q * 4];
    }
    {
        uint32_t AH = SB + AH_O, AL = SB + AL_O, BH = SB + BH_O, BL = SB + BL_O;
#pragma unroll
        for (int j = 0; j < 4; j++) {
            int s = tid + j * NTHR;
            cvtst(ra[j], AH, AL, s >> 4, s & 15);
            cvtst(rb[j], BH, BL, s >> 4, s & 15);
        }
    }
    __syncthreads();
#pragma unroll
    for (int j = 0; j < 4; j++) {
        int s = tid + j * NTHR, r = s >> 4, q = s & 15;
        ra[j] = *(const float4*)&x[(size_t)(m0 + r) * H_DIM + KC + q * 4];
        rb[j] = *(const float4*)&w[(size_t)r * H_DIM + KC + q * 4];
    }

#pragma unroll 1
    for (int c = 0; c < NC - 2; c++)
        chunk_iter<true, true>(c, x, w, m0, tid, kgrp, SB, ra, rb,
                               sxor, aoff0, aoff1, akx, boff0, boff1, bkx, acc);
    chunk_iter<true,  false>(NC - 2, x, w, m0, tid, kgrp, SB, ra, rb,
                             sxor, aoff0, aoff1, akx, boff0, boff1, bkx, acc);
    chunk_iter<false, false>(NC - 1, x, w, m0, tid, kgrp, SB, ra, rb,
                             sxor, aoff0, aoff1, akx, boff0, boff1, bkx, acc);

    // ---- merge kgrp halves + stage logits [64][65] (overlays stage0) ----
    float* ls = (float*)(dsm_raw + (SB - raw));
    {
        int gr = lid >> 2, tg = lid & 3;
        if (kgrp == 0) {
#pragma unroll
            for (int mi = 0; mi < 2; mi++)
#pragma unroll
                for (int ni = 0; ni < 4; ni++) {
                    int r0 = wm * 32 + mi * 16 + gr;
                    int col = wn * 32 + ni * 8 + tg * 2;
                    ls[r0 * 65 + col]           = acc[mi][ni][0];
                    ls[r0 * 65 + col + 1]       = acc[mi][ni][1];
                    ls[(r0 + 8) * 65 + col]     = acc[mi][ni][2];
                    ls[(r0 + 8) * 65 + col + 1] = acc[mi][ni][3];
                }
        }
        __syncthreads();
        if (kgrp == 1) {
#pragma unroll
            for (int mi = 0; mi < 2; mi++)
#pragma unroll
                for (int ni = 0; ni < 4; ni++) {
                    int r0 = wm * 32 + mi * 16 + gr;
                    int col = wn * 32 + ni * 8 + tg * 2;
                    ls[r0 * 65 + col]           += acc[mi][ni][0];
                    ls[r0 * 65 + col + 1]       += acc[mi][ni][1];
                    ls[(r0 + 8) * 65 + col]     += acc[mi][ni][2];
                    ls[(r0 + 8) * 65 + col + 1] += acc[mi][ni][3];
                }
        }
        __syncthreads();
    }

    // ---- per-token epilogue: threads 0..63 own one token ----
    float zs = 0.f;
    if (tid < MT) {
        float m1 = -1e30f, m2 = -1e30f, m3 = -1e30f;
        int i1 = 0, i2 = 0;
#pragma unroll
        for (int j = 0; j < E_NUM; j++) {
            float v = ls[tid * 65 + j];
            zs += v * v;
            if (v > m1)      { m3 = m2; m2 = m1; i2 = i1; m1 = v; i1 = j; }
            else if (v > m2) { m3 = m2; m2 = v; i2 = j; }
            else if (v > m3) { m3 = v; }
        }
        float s = 0.f;
#pragma unroll
        for (int j = 0; j < E_NUM; j++)
            s += expf(ls[tid * 65 + j] - m1);

        int tok = m0 + tid;
        out[tok * 2 + 0] = (float)i1;
        out[tok * 2 + 1] = (float)i2;
        out[2 * M_TOT + tok * 2 + 0] = 1.0f / s;
        out[2 * M_TOT + tok * 2 + 1] = expf(m2 - m1) / s;
        if ((m1 - m2 < GAP_TH) || (m2 - m3 < GAP_TH)) {
            int p = atomicAdd(&fcnt, 1);
            if (p < 16) flist[p] = tid;
        }
    }

    // ---- z partial ----
    if (wid < 2) {
#pragma unroll
        for (int o = 16; o > 0; o >>= 1)
            zs += __shfl_xor_sync(0xffffffffu, zs, o);
        if (lid == 0) zsh[wid] = zs;
    }
    __syncthreads();
    if (tid == 0)
        g_partials[blockIdx.x] = zsh[0] + zsh[1];

    // ---- inline exact fp32 fixup for ambiguous tokens (rare) ----
    int nfix = fcnt < 16 ? fcnt : 16;
    for (int i = 0; i < nfix; i++) {
        int tok = m0 + flist[i];
        const float4* xr = (const float4*)(x + (size_t)tok * H_DIM);
#pragma unroll 1
        for (int e8 = 0; e8 < 8; e8++) {
            int e = wid * 8 + e8;
            const float4* wr = (const float4*)(w + (size_t)e * H_DIM);
            float s = 0.f;
#pragma unroll 4
            for (int j = lid; j < H_DIM / 4; j += 32) {
                float4 a = xr[j], b = wr[j];
                s += a.x * b.x + a.y * b.y + a.z * b.z + a.w * b.w;
            }
#pragma unroll
            for (int o = 16; o > 0; o >>= 1)
                s += __shfl_xor_sync(0xffffffffu, s, o);
            if (lid == 0) lg[e] = s;
        }
        __syncthreads();
        if (tid == 0) {
            float m1 = -1e30f, m2 = -1e30f;
            int i1 = 0, i2 = 0;
            for (int j = 0; j < E_NUM; j++) {
                float v = lg[j];
                if (v > m1)      { m2 = m1; i2 = i1; m1 = v; i1 = j; }
                else if (v > m2) { m2 = v; i2 = j; }
            }
            float s2 = 0.f;
            for (int j = 0; j < E_NUM; j++) s2 += expf(lg[j] - m1);
            out[tok * 2 + 0] = (float)i1;
            out[tok * 2 + 1] = (float)i2;
            out[2 * M_TOT + tok * 2 + 0] = 1.0f / s2;
            out[2 * M_TOT + tok * 2 + 1] = expf(m2 - m1) / s2;
        }
        __syncthreads();
    }
}

__global__ __launch_bounds__(256) void router_finalize(float* __restrict__ out)
{
    __shared__ float sh[256];
    int tid = threadIdx.x;
    sh[tid] = g_partials[tid];             // NBLK == 256
    __syncthreads();
#pragma unroll
    for (int s = 128; s > 0; s >>= 1) {
        if (tid < s) sh[tid] += sh[tid + s];
        __syncthreads();
    }
    if (tid == 0) {
        out[4 * M_TOT + 0] = 0.0f;
        out[4 * M_TOT + 1] = sh[0] / ((float)M_TOT * (float)E_NUM);
    }
}

extern "C" void kernel_launch(void* const* d_in, const int* in_sizes, int n_in,
                              void* d_out, int out_size)
{
    const float* x = (const float*)d_in[0];   // [4,4096,4096]
    const float* w = (const float*)d_in[1];   // [64,4096]
    float* out = (float*)d_out;

    cudaFuncSetAttribute(router_main, cudaFuncAttributeMaxDynamicSharedMemorySize, DSMB);
    router_main<<<NBLK, NTHR, DSMB>>>(x, w, out);
    router_finalize<<<1, 256>>>(out);
}

// round 12
// speedup vs baseline: 1.0615x; 1.0338x over previous
#include <cuda_runtime.h>
#include <cuda_bf16.h>
#include <math.h>
#include <stdint.h>

// TopKRouter: x[4,4096,4096] fp32, gate_w[64,4096] fp32
// logits = x @ w^T [16384,64]; softmax; top-2; z_loss = mean(logits^2)
// out fp32: [0,32768) idx | [32768,65536) scores | [65536] aux=0 | [65537] z_loss
//
// sm_103 BASE target. mma.sync bf16 hi/lo split (3 passes).
// A operand: direct LDG of fragment-pattern float2s -> register cvt (NO smem).
// B operand: smem staged (tiny), double-buffered, verified ldmatrix path.
// MT=64/CTA, 256 thr, grid=256, 2 CTAs/SM.

#define M_TOT 16384
#define H_DIM 4096
#define E_NUM 64
#define MT    64
#define KC    64
#define NC    (H_DIM / KC)     // 64
#define NBLK  (M_TOT / MT)     // 256
#define NTHR  256
#define GAP_TH 3e-4f

// B stage: BH 0 | BL 8192 ; stage size 16 KB; two stages
#define BH_O 0
#define BL_O 8192
#define BSTG 16384
#define DSMB (1024 + 2 * BSTG)   // 33792 (logits [64][65] overlays stages later)

__device__ float g_partials[NBLK];

__device__ __forceinline__ uint32_t smem_u32(const void* p) {
    uint32_t a;
    asm("{ .reg .u64 t; cvta.to.shared.u64 t, %1; cvt.u32.u64 %0, t; }" : "=r"(a) : "l"(p));
    return a;
}

#define LDM4(r, a) \
    asm volatile("ldmatrix.sync.aligned.m8n8.x4.shared.b16 {%0,%1,%2,%3}, [%4];" \
        : "=r"((r)[0]), "=r"((r)[1]), "=r"((r)[2]), "=r"((r)[3]) : "r"(a))

#define MMA(c, a, b0, b1) \
    asm volatile("mma.sync.aligned.m16n8k16.row.col.f32.bf16.bf16.f32 " \
        "{%0,%1,%2,%3},{%4,%5,%6,%7},{%8,%9},{%0,%1,%2,%3};" \
        : "+f"((c)[0]), "+f"((c)[1]), "+f"((c)[2]), "+f"((c)[3]) \
        : "r"((a)[0]), "r"((a)[1]), "r"((a)[2]), "r"((a)[3]), "r"(b0), "r"(b1))

// split float4 into bf16 hi/lo quads, store 8B each (swizzled, 128B rows) — B path
__device__ __forceinline__ void cvtst(float4 v, uint32_t hi, uint32_t lo, int row, int q) {
    uint32_t off = (uint32_t)row * 128u + (((uint32_t)q * 8u) ^ (((uint32_t)row & 7u) << 4));
    uint32_t h01, h23, l01, l23;
    asm("cvt.rn.bf16x2.f32 %0, %1, %2;" : "=r"(h01) : "f"(v.y), "f"(v.x));
    asm("cvt.rn.bf16x2.f32 %0, %1, %2;" : "=r"(h23) : "f"(v.w), "f"(v.z));
    float hx = __uint_as_float(h01 << 16), hy = __uint_as_float(h01 & 0xffff0000u);
    float hz = __uint_as_float(h23 << 16), hw = __uint_as_float(h23 & 0xffff0000u);
    asm("cvt.rn.bf16x2.f32 %0, %1, %2;" : "=r"(l01) : "f"(v.y - hy), "f"(v.x - hx));
    asm("cvt.rn.bf16x2.f32 %0, %1, %2;" : "=r"(l23) : "f"(v.w - hw), "f"(v.z - hz));
    asm volatile("st.shared.v2.u32 [%0], {%1,%2};" :: "r"(hi + off), "r"(h01), "r"(h23) : "memory");
    asm volatile("st.shared.v2.u32 [%0], {%1,%2};" :: "r"(lo + off), "r"(l01), "r"(l23) : "memory");
}

// convert one float2 (k-adjacent pair) to bf16x2 hi + lo (elem0 in low half)
__device__ __forceinline__ void cvt2(float2 v, uint32_t& h, uint32_t& l) {
    asm("cvt.rn.bf16x2.f32 %0, %1, %2;" : "=r"(h) : "f"(v.y), "f"(v.x));
    float hx = __uint_as_float(h << 16), hy = __uint_as_float(h & 0xffff0000u);
    asm("cvt.rn.bf16x2.f32 %0, %1, %2;" : "=r"(l) : "f"(v.y - hy), "f"(v.x - hx));
}

extern __shared__ char dsm_raw[];

__global__ __launch_bounds__(NTHR, 2)
void router_main(const float* __restrict__ x, const float* __restrict__ w,
                 float* __restrict__ out)
{
    __shared__ float zsh[2];
    __shared__ float lg[E_NUM];
    __shared__ int flist[16];
    __shared__ int fcnt;

    const int tid  = threadIdx.x;
    const int lid  = tid & 31;
    const int wid  = tid >> 5;               // 0..7
    const int wm   = wid & 1;                // row half (32 tokens)
    const int wn   = (wid >> 1) & 1;         // expert half (32 experts)
    const int kgrp = wid >> 2;               // k half of each chunk (k32)
    const int m0   = blockIdx.x * MT;
    const int kw   = kgrp * 32;

    uint32_t raw = smem_u32(dsm_raw);
    uint32_t SB  = (raw + 127u) & ~127u;

    // B ldmatrix constants (verified path, unchanged)
    const uint32_t sxor  = ((uint32_t)(lid & 7)) << 4;
    const uint32_t boff0 = (uint32_t)(wn * 32 + ((lid >> 4) << 3) + (lid & 7)) * 128u;
    const uint32_t boff1 = boff0 + 2048u;    // +16 experts
    const uint32_t bkx   = ((uint32_t)((lid >> 3) & 1)) << 4;

    // A fragment base pointer: row = m0 + wm*32 + (lid>>2), col base = 2*(lid&3)
    const float* aptr = x + (size_t)(m0 + wm * 32 + (lid >> 2)) * H_DIM + 2 * (lid & 3);

    // B staging lanes: row = (tid>>4) + slot*16, q = tid&15
    const int brow = tid >> 4, bq = tid & 15;

    float acc[2][4][4];
#pragma unroll
    for (int mi = 0; mi < 2; mi++)
#pragma unroll
        for (int ni = 0; ni < 4; ni++)
#pragma unroll
            for (int r = 0; r < 4; r++) acc[mi][ni][r] = 0.f;

    if (tid == 0) fcnt = 0;

    float2 S0[8], S1[8];     // A fp32 frags: [mi*4 + j], j = (g,2t)(g+8,2t)(g,2t+8)(g+8,2t+8)
    float4 rb[4];            // B fp32 for next chunk

    // ---------- prologue ----------
#pragma unroll
    for (int slot = 0; slot < 4; slot++)
        rb[slot] = *(const float4*)&w[(size_t)(brow + slot * 16) * H_DIM + bq * 4];
    {
        uint32_t st0 = SB;   // chunk 0 reads stage 0
#pragma unroll
        for (int slot = 0; slot < 4; slot++)
            cvtst(rb[slot], st0 + BH_O, st0 + BL_O, brow + slot * 16, bq);
    }
#pragma unroll
    for (int mi = 0; mi < 2; mi++) {
        S0[mi * 4 + 0] = *(const float2*)(aptr + (mi * 16 + 0) * H_DIM + kw + 0);
        S0[mi * 4 + 1] = *(const float2*)(aptr + (mi * 16 + 8) * H_DIM + kw + 0);
        S0[mi * 4 + 2] = *(const float2*)(aptr + (mi * 16 + 0) * H_DIM + kw + 8);
        S0[mi * 4 + 3] = *(const float2*)(aptr + (mi * 16 + 8) * H_DIM + kw + 8);
        S1[mi * 4 + 0] = *(const float2*)(aptr + (mi * 16 + 0) * H_DIM + kw + 16);
        S1[mi * 4 + 1] = *(const float2*)(aptr + (mi * 16 + 8) * H_DIM + kw + 16);
        S1[mi * 4 + 2] = *(const float2*)(aptr + (mi * 16 + 0) * H_DIM + kw + 24);
        S1[mi * 4 + 3] = *(const float2*)(aptr + (mi * 16 + 8) * H_DIM + kw + 24);
    }
#pragma unroll
    for (int slot = 0; slot < 4; slot++)                       // B of chunk 1
        rb[slot] = *(const float4*)&w[(size_t)(brow + slot * 16) * H_DIM + KC + bq * 4];
    __syncthreads();

    // ---------- main loop ----------
#pragma unroll 1
    for (int c = 0; c < NC; c++) {
        const uint32_t rbuf = SB + ((c & 1) ? BSTG : 0);
        const uint32_t wbuf = SB + ((c & 1) ? 0 : BSTG);
        const uint32_t BH = rbuf + BH_O, BL = rbuf + BL_O;
        const int kc = c * KC + kw;
        const int kA = (c < NC - 1) ? (kc + KC) : kc;          // clamped A prefetch
        const int kB = (c < NC - 2) ? ((c + 2) * KC) : ((NC - 1) * KC);

#pragma unroll
        for (int ks = 0; ks < 2; ks++) {
            float2* S = ks ? S1 : S0;
            // convert current A slice -> frags (frees S), then prefetch next chunk's slice
            uint32_t ah[2][4], al[2][4];
#pragma unroll
            for (int mi = 0; mi < 2; mi++)
#pragma unroll
                for (int j = 0; j < 4; j++)
                    cvt2(S[mi * 4 + j], ah[mi][j], al[mi][j]);
            {
                const int kk = kA + ks * 16;
#pragma unroll
                for (int mi = 0; mi < 2; mi++) {
                    S[mi * 4 + 0] = *(const float2*)(aptr + (mi * 16 + 0) * H_DIM + kk + 0);
                    S[mi * 4 + 1] = *(const float2*)(aptr + (mi * 16 + 8) * H_DIM + kk + 0);
                    S[mi * 4 + 2] = *(const float2*)(aptr + (mi * 16 + 0) * H_DIM + kk + 8);
                    S[mi * 4 + 3] = *(const float2*)(aptr + (mi * 16 + 8) * H_DIM + kk + 8);
                }
            }
            // B ldmatrix + MMAs
            const uint32_t kb  = (uint32_t)(kgrp * 2 + ks) * 32u;
            const uint32_t kbb = (kb + bkx) ^ sxor;
#pragma unroll
            for (int nh = 0; nh < 2; nh++) {
                const uint32_t bo = (nh == 0) ? boff0 : boff1;
                uint32_t bHn[4], bLn[4];
                LDM4(bHn, BH + bo + kbb);
                LDM4(bLn, BL + bo + kbb);
#pragma unroll
                for (int mi = 0; mi < 2; mi++)
#pragma unroll
                    for (int nl = 0; nl < 2; nl++)
                        MMA(acc[mi][nh * 2 + nl], ah[mi], bHn[nl * 2], bHn[nl * 2 + 1]);
#pragma unroll
                for (int mi = 0; mi < 2; mi++)
#pragma unroll
                    for (int nl = 0; nl < 2; nl++)
                        MMA(acc[mi][nh * 2 + nl], ah[mi], bLn[nl * 2], bLn[nl * 2 + 1]);
#pragma unroll
                for (int mi = 0; mi < 2; mi++)
#pragma unroll
                    for (int nl = 0; nl < 2; nl++)
                        MMA(acc[mi][nh * 2 + nl], al[mi], bHn[nl * 2], bHn[nl * 2 + 1]);
            }
        }

        // stage B(c+1) from rb, then LDG B(c+2)
#pragma unroll
        for (int slot = 0; slot < 4; slot++)
            cvtst(rb[slot], wbuf + BH_O, wbuf + BL_O, brow + slot * 16, bq);
#pragma unroll
        for (int slot = 0; slot < 4; slot++)
            rb[slot] = *(const float4*)&w[(size_t)(brow + slot * 16) * H_DIM + kB + bq * 4];
        __syncthreads();
    }

    // ---------- merge kgrp halves + stage logits [64][65] (overlays B stages) ----------
    float* ls = (float*)(dsm_raw + (SB - raw));
    {
        int gr = lid >> 2, tg = lid & 3;
        if (kgrp == 0) {
#pragma unroll
            for (int mi = 0; mi < 2; mi++)
#pragma unroll
                for (int ni = 0; ni < 4; ni++) {
                    int r0 = wm * 32 + mi * 16 + gr;
                    int col = wn * 32 + ni * 8 + tg * 2;
                    ls[r0 * 65 + col]           = acc[mi][ni][0];
                    ls[r0 * 65 + col + 1]       = acc[mi][ni][1];
                    ls[(r0 + 8) * 65 + col]     = acc[mi][ni][2];
                    ls[(r0 + 8) * 65 + col + 1] = acc[mi][ni][3];
                }
        }
        __syncthreads();
        if (kgrp == 1) {
#pragma unroll
            for (int mi = 0; mi < 2; mi++)
#pragma unroll
                for (int ni = 0; ni < 4; ni++) {
                    int r0 = wm * 32 + mi * 16 + gr;
                    int col = wn * 32 + ni * 8 + tg * 2;
                    ls[r0 * 65 + col]           += acc[mi][ni][0];
                    ls[r0 * 65 + col + 1]       += acc[mi][ni][1];
                    ls[(r0 + 8) * 65 + col]     += acc[mi][ni][2];
                    ls[(r0 + 8) * 65 + col + 1] += acc[mi][ni][3];
                }
        }
        __syncthreads();
    }

    // ---------- per-token epilogue: threads 0..63 own one token ----------
    float zs = 0.f;
    if (tid < MT) {
        float m1 = -1e30f, m2 = -1e30f, m3 = -1e30f;
        int i1 = 0, i2 = 0;
#pragma unroll
        for (int j = 0; j < E_NUM; j++) {
            float v = ls[tid * 65 + j];
            zs += v * v;
            if (v > m1)      { m3 = m2; m2 = m1; i2 = i1; m1 = v; i1 = j; }
            else if (v > m2) { m3 = m2; m2 = v; i2 = j; }
            else if (v > m3) { m3 = v; }
        }
        float s = 0.f;
#pragma unroll
        for (int j = 0; j < E_NUM; j++)
            s += expf(ls[tid * 65 + j] - m1);

        int tok = m0 + tid;
        out[tok * 2 + 0] = (float)i1;
        out[tok * 2 + 1] = (float)i2;
        out[2 * M_TOT + tok * 2 + 0] = 1.0f / s;
        out[2 * M_TOT + tok * 2 + 1] = expf(m2 - m1) / s;
        if ((m1 - m2 < GAP_TH) || (m2 - m3 < GAP_TH)) {
            int p = atomicAdd(&fcnt, 1);
            if (p < 16) flist[p] = tid;
        }
    }

    // ---------- z partial ----------
    if (wid < 2) {
#pragma unroll
        for (int o = 16; o > 0; o >>= 1)
            zs += __shfl_xor_sync(0xffffffffu, zs, o);
        if (lid == 0) zsh[wid] = zs;
    }
    __syncthreads();
    if (tid == 0)
        g_partials[blockIdx.x] = zsh[0] + zsh[1];

    // ---------- inline exact fp32 fixup for ambiguous tokens (rare) ----------
    int nfix = fcnt < 16 ? fcnt : 16;
    for (int i = 0; i < nfix; i++) {
        int tok = m0 + flist[i];
        const float4* xr = (const float4*)(x + (size_t)tok * H_DIM);
#pragma unroll 1
        for (int e8 = 0; e8 < 8; e8++) {
            int e = wid * 8 + e8;
            const float4* wr = (const float4*)(w + (size_t)e * H_DIM);
            float s = 0.f;
#pragma unroll 4
            for (int j = lid; j < H_DIM / 4; j += 32) {
                float4 a = xr[j], b = wr[j];
                s += a.x * b.x + a.y * b.y + a.z * b.z + a.w * b.w;
            }
#pragma unroll
            for (int o = 16; o > 0; o >>= 1)
                s += __shfl_xor_sync(0xffffffffu, s, o);
            if (lid == 0) lg[e] = s;
        }
        __syncthreads();
        if (tid == 0) {
            float m1 = -1e30f, m2 = -1e30f;
            int i1 = 0, i2 = 0;
            for (int j = 0; j < E_NUM; j++) {
                float v = lg[j];
                if (v > m1)      { m2 = m1; i2 = i1; m1 = v; i1 = j; }
                else if (v > m2) { m2 = v; i2 = j; }
            }
            float s2 = 0.f;
            for (int j = 0; j < E_NUM; j++) s2 += expf(lg[j] - m1);
            out[tok * 2 + 0] = (float)i1;
            out[tok * 2 + 1] = (float)i2;
            out[2 * M_TOT + tok * 2 + 0] = 1.0f / s2;
            out[2 * M_TOT + tok * 2 + 1] = expf(m2 - m1) / s2;
        }
        __syncthreads();
    }
}

__global__ __launch_bounds__(256) void router_finalize(float* __restrict__ out)
{
    __shared__ float sh[256];
    int tid = threadIdx.x;
    sh[tid] = g_partials[tid];             // NBLK == 256
    __syncthreads();
#pragma unroll
    for (int s = 128; s > 0; s >>= 1) {
        if (tid < s) sh[tid] += sh[tid + s];
        __syncthreads();
    }
    if (tid == 0) {
        out[4 * M_TOT + 0] = 0.0f;
        out[4 * M_TOT + 1] = sh[0] / ((float)M_TOT * (float)E_NUM);
    }
}

extern "C" void kernel_launch(void* const* d_in, const int* in_sizes, int n_in,
                              void* d_out, int out_size)
{
    const float* x = (const float*)d_in[0];   // [4,4096,4096]
    const float* w = (const float*)d_in[1];   // [64,4096]
    float* out = (float*)d_out;

    cudaFuncSetAttribute(router_main, cudaFuncAttributeMaxDynamicSharedMemorySize, DSMB);
    router_main<<<NBLK, NTHR, DSMB>>>(x, w, out);
    router_finalize<<<1, 256>>>(out);
}